// round 3
// baseline (speedup 1.0000x reference)
#include <cuda_runtime.h>
#include <cstdint>

#define D 128
#define NN_MAX 50000
#define NGRAPH 64
#define NCLASS 16

// ---------------- device scratch (allocation-free, aligned for vector ops) ----------------
__device__ __align__(256) float g_h [NN_MAX * D];
__device__ __align__(256) float g_t [NN_MAX * D];
__device__ __align__(256) float g_m [NN_MAX * D];
__device__ __align__(256) float g_z [NN_MAX * D];
__device__ __align__(256) float g_r [NN_MAX * D];
__device__ __align__(256) float g_ci[NN_MAX * D];
__device__ __align__(256) float g_g [NN_MAX * D];
__device__ __align__(256) float g_pmax[NGRAPH * D];
__device__ __align__(256) float g_psum[NGRAPH * D];
__device__ __align__(256) float g_cnt [NGRAPH];

__device__ __forceinline__ float sigf(float x) { return 1.0f / (1.0f + __expf(-x)); }

// ---------------- GEMM: C = act((ACCUM?C:0) + A[N,128] @ W[128,128] + bias + bias2) ----------------
template<bool ACCUM, int ACT>  // ACT: 0 none, 1 sigmoid, 2 relu
__global__ void __launch_bounds__(256) gemm128(
    const float* __restrict__ A, const float* __restrict__ W,
    const float* __restrict__ bias, const float* __restrict__ bias2,
    float* __restrict__ C, int N)
{
    __shared__ float As[16][132];  // padded: kills store bank conflicts
    __shared__ float Ws[16][128];

    const int tid  = threadIdx.x;
    const int row0 = blockIdx.x * 128;
    const int tx   = tid & 15;   // col group: cols tx*8 .. +7
    const int ty   = tid >> 4;   // row group: rows ty*8 .. +7

    float acc[8][8];
#pragma unroll
    for (int i = 0; i < 8; i++)
#pragma unroll
        for (int j = 0; j < 8; j++) acc[i][j] = 0.f;

    for (int kc = 0; kc < D; kc += 16) {
#pragma unroll
        for (int i = 0; i < 8; i++) {
            int lin = tid + i * 256;
            int r = lin >> 4, k = lin & 15;
            int grow = row0 + r;
            As[k][r] = (grow < N) ? A[(size_t)grow * D + kc + k] : 0.f;
        }
#pragma unroll
        for (int i = 0; i < 8; i++) {
            int lin = tid + i * 256;
            int k = lin >> 7, c = lin & 127;
            Ws[k][c] = W[(size_t)(kc + k) * D + c];
        }
        __syncthreads();
#pragma unroll
        for (int kk = 0; kk < 16; kk++) {
            float a[8], w[8];
#pragma unroll
            for (int i = 0; i < 8; i++) a[i] = As[kk][ty * 8 + i];
#pragma unroll
            for (int j = 0; j < 8; j++) w[j] = Ws[kk][tx * 8 + j];
#pragma unroll
            for (int i = 0; i < 8; i++)
#pragma unroll
                for (int j = 0; j < 8; j++) acc[i][j] += a[i] * w[j];
        }
        __syncthreads();
    }

#pragma unroll
    for (int i = 0; i < 8; i++) {
        int grow = row0 + ty * 8 + i;
        if (grow >= N) continue;
#pragma unroll
        for (int j = 0; j < 8; j++) {
            int col = tx * 8 + j;
            float v = acc[i][j];
            if (bias)  v += bias[col];
            if (bias2) v += bias2[col];
            if (ACCUM) v += C[(size_t)grow * D + col];
            if (ACT == 1) v = sigf(v);
            if (ACT == 2) v = fmaxf(v, 0.f);
            C[(size_t)grow * D + col] = v;
        }
    }
}

// ---------------- simple elementwise kernels ----------------
__global__ void copy_kernel(const float* __restrict__ src, float* __restrict__ dst, int n4) {
    int i = blockIdx.x * blockDim.x + threadIdx.x;
    if (i < n4) ((float4*)dst)[i] = ((const float4*)src)[i];
}

__global__ void mul_kernel(float* __restrict__ a, const float* __restrict__ b, int n) {
    int i = blockIdx.x * blockDim.x + threadIdx.x;
    if (i < n) a[i] *= b[i];
}

// h = z*(g1*sigmoid(g2)) + (1-z)*h
__global__ void combine_kernel(float* __restrict__ h, const float* __restrict__ z,
                               const float* __restrict__ g1, const float* __restrict__ g2, int n) {
    int i = blockIdx.x * blockDim.x + threadIdx.x;
    if (i < n) {
        float zz = z[i];
        float ht = g1[i] * sigf(g2[i]);
        h[i] = zz * ht + (1.f - zz) * h[i];
    }
}

// ---------------- edge scatter: m[dst] += t[src] * ew   (edge_index is INT32) ----------------
__global__ void scatter_kernel(const int* __restrict__ ei, const float* __restrict__ ew,
                               const float* __restrict__ t, float* __restrict__ m, int E) {
    long long idx = (long long)blockIdx.x * blockDim.x + threadIdx.x;
    int e = (int)(idx >> 5);
    if (e >= E) return;
    int lane = (int)(idx & 31);
    int s = ei[e];
    int d = ei[(size_t)E + e];
    float w = ew[e];
    float4 v = *(const float4*)(t + (size_t)s * D + lane * 4);
    float4 r;
    r.x = v.x * w; r.y = v.y * w; r.z = v.z * w; r.w = v.w * w;
    float* p = m + (size_t)d * D + lane * 4;
    asm volatile("red.global.add.v4.f32 [%0], {%1,%2,%3,%4};"
                 :: "l"(p), "f"(r.x), "f"(r.y), "f"(r.z), "f"(r.w) : "memory");
}

// ---------------- head: attention gate + scale ----------------
__global__ void att_kernel(const float* __restrict__ h, const float* __restrict__ Wag,
                           const float* __restrict__ bag, float* __restrict__ out, int N) {
    long long idx = (long long)blockIdx.x * blockDim.x + threadIdx.x;
    int node = (int)(idx >> 5);
    if (node >= N) return;
    int lane = (int)(idx & 31);
    float4 hv = *(const float4*)(h + (size_t)node * D + lane * 4);
    float4 wv = *(const float4*)(Wag + lane * 4);
    float s = hv.x * wv.x + hv.y * wv.y + hv.z * wv.z + hv.w * wv.w;
#pragma unroll
    for (int o = 16; o > 0; o >>= 1) s += __shfl_xor_sync(0xFFFFFFFF, s, o);
    float att = sigf(s + bag[0]);
    float4 r;
    r.x = hv.x * att; r.y = hv.y * att; r.z = hv.z * att; r.w = hv.w * att;
    *(float4*)(out + (size_t)node * D + lane * 4) = r;
}

// ---------------- pooling (batch is INT32) ----------------
__global__ void zero_pool_kernel(float* pmax, float* psum, float* cnt) {
    int i = blockIdx.x * blockDim.x + threadIdx.x;
    if (i < NGRAPH * D) { pmax[i] = 0.f; psum[i] = 0.f; }
    if (i < NGRAPH) cnt[i] = 0.f;
}

__global__ void pool_kernel(const float* __restrict__ h2, const int* __restrict__ batch,
                            float* __restrict__ pmax, float* __restrict__ psum,
                            float* __restrict__ cnt, int N) {
    long long idx = (long long)blockIdx.x * blockDim.x + threadIdx.x;
    int node = (int)(idx >> 5);
    if (node >= N) return;
    int lane = (int)(idx & 31);
    int g = batch[node];
    float4 v = *(const float4*)(h2 + (size_t)node * D + lane * 4);
    int* pm = (int*)(pmax + (size_t)g * D + lane * 4);
    atomicMax(pm + 0, __float_as_int(v.x));   // h2 >= 0 so int order == float order
    atomicMax(pm + 1, __float_as_int(v.y));
    atomicMax(pm + 2, __float_as_int(v.z));
    atomicMax(pm + 3, __float_as_int(v.w));
    float* ps = psum + (size_t)g * D + lane * 4;
    asm volatile("red.global.add.v4.f32 [%0], {%1,%2,%3,%4};"
                 :: "l"(ps), "f"(v.x), "f"(v.y), "f"(v.z), "f"(v.w) : "memory");
    if (lane == 0) atomicAdd(cnt + g, 1.0f);
}

// ---------------- final MLP over pooled features ----------------
__global__ void mlp_kernel(const float* __restrict__ pmax, const float* __restrict__ psum,
                           const float* __restrict__ cnt,
                           const float* __restrict__ W1, const float* __restrict__ b1,
                           const float* __restrict__ W2, const float* __restrict__ b2,
                           float* __restrict__ out) {
    __shared__ float xp[2 * D];
    __shared__ float hid[D];
    int g = blockIdx.x;
    int t = threadIdx.x;  // 128 threads
    float c = fmaxf(cnt[g], 1.0f);
    xp[t]     = fmaxf(pmax[(size_t)g * D + t], 0.0f);
    xp[D + t] = psum[(size_t)g * D + t] / c;
    __syncthreads();
    float acc = b1[t];
#pragma unroll 8
    for (int j = 0; j < 2 * D; j++) acc += xp[j] * W1[(size_t)j * D + t];
    hid[t] = fmaxf(acc, 0.f);
    __syncthreads();
    if (t < NCLASS) {
        float o = b2[t];
#pragma unroll 8
        for (int k = 0; k < D; k++) o += hid[k] * W2[(size_t)k * NCLASS + t];
        out[(size_t)g * NCLASS + t] = o;
    }
}

// ---------------- host orchestration ----------------
static void launch_gemm(const float* A, const float* W, const float* bias, const float* bias2,
                        float* C, int N, bool accum, int act) {
    dim3 grid((N + 127) / 128);
    if (!accum && act == 0)      gemm128<false, 0><<<grid, 256>>>(A, W, bias, bias2, C, N);
    else if (accum && act == 1)  gemm128<true,  1><<<grid, 256>>>(A, W, bias, bias2, C, N);
    else if (accum && act == 0)  gemm128<true,  0><<<grid, 256>>>(A, W, bias, bias2, C, N);
    else                         gemm128<false, 2><<<grid, 256>>>(A, W, bias, bias2, C, N);
}

extern "C" void kernel_launch(void* const* d_in, const int* in_sizes, int n_in,
                              void* d_out, int out_size) {
    const float* x     = (const float*)d_in[0];
    const int*   ei    = (const int*)d_in[1];    // int32 (jax x64 disabled)
    const int*   batch = (const int*)d_in[2];    // int32
    const float* ew    = (const float*)d_in[3];
    const float* Wa    = (const float*)d_in[4];
    const float *Wzm = (const float*)d_in[5],  *bzm = (const float*)d_in[6];
    const float *Wzs = (const float*)d_in[7],  *bzs = (const float*)d_in[8];
    const float *Wrm = (const float*)d_in[9],  *brm = (const float*)d_in[10];
    const float *Wrs = (const float*)d_in[11], *brs = (const float*)d_in[12];
    const float *Whm = (const float*)d_in[13], *bhm = (const float*)d_in[14];
    const float *Whs = (const float*)d_in[15], *bhs = (const float*)d_in[16];
    const float *Whg = (const float*)d_in[17], *bhg = (const float*)d_in[18];
    const float *Whl = (const float*)d_in[19], *bhl = (const float*)d_in[20];
    const float *bias_z = (const float*)d_in[21];
    const float *bias_r = (const float*)d_in[22];
    const float *bias_h = (const float*)d_in[23];
    const float *Wag = (const float*)d_in[24], *bag = (const float*)d_in[25];
    const float *Wae = (const float*)d_in[26], *bae = (const float*)d_in[27];
    const float *W1  = (const float*)d_in[28], *b1  = (const float*)d_in[29];
    const float *W2  = (const float*)d_in[30], *b2  = (const float*)d_in[31];
    float* out = (float*)d_out;

    const int N = in_sizes[0] / D;
    const int E = in_sizes[3];

    float *h, *t, *m, *z, *r, *ci, *g, *pmax, *psum, *cnt;
    cudaGetSymbolAddress((void**)&h,  g_h);
    cudaGetSymbolAddress((void**)&t,  g_t);
    cudaGetSymbolAddress((void**)&m,  g_m);
    cudaGetSymbolAddress((void**)&z,  g_z);
    cudaGetSymbolAddress((void**)&r,  g_r);
    cudaGetSymbolAddress((void**)&ci, g_ci);
    cudaGetSymbolAddress((void**)&g,  g_g);
    cudaGetSymbolAddress((void**)&pmax, g_pmax);
    cudaGetSymbolAddress((void**)&psum, g_psum);
    cudaGetSymbolAddress((void**)&cnt,  g_cnt);

    const int ND = N * D;
    const int n4 = ND / 4;
    const int EB = 256;

    // h = x
    copy_kernel<<<(n4 + 255) / 256, 256>>>(x, h, n4);

    for (int layer = 0; layer < 3; layer++) {
        // t = h @ Wa
        launch_gemm(h, Wa, nullptr, nullptr, t, N, false, 0);
        // m = t (self loops, weight 1)
        copy_kernel<<<(n4 + 255) / 256, 256>>>(t, m, n4);
        // m[dst] += t[src] * ew
        {
            long long work = (long long)E * 32;
            scatter_kernel<<<(unsigned)((work + EB - 1) / EB), EB>>>(ei, ew, t, m, E);
        }
        // z = sigmoid(m@Wzm + bzm + h@Wzs + bzs + bias_z)
        launch_gemm(m, Wzm, bzm, nullptr, z, N, false, 0);
        launch_gemm(h, Wzs, bzs, bias_z, z, N, true, 1);
        // r = sigmoid(m@Wrm + brm + h@Wrs + brs + bias_r)
        launch_gemm(m, Wrm, brm, nullptr, r, N, false, 0);
        launch_gemm(h, Wrs, brs, bias_r, r, N, true, 1);
        // ci = m@Whm + bhm + (r*h)@Whs + bhs + bias_h
        launch_gemm(m, Whm, bhm, nullptr, ci, N, false, 0);
        mul_kernel<<<(ND + 255) / 256, 256>>>(r, h, ND);  // r <- r*h
        launch_gemm(r, Whs, bhs, bias_h, ci, N, true, 0);
        // g1 = ci@Whl + bhl (into t), g2 = ci@Whg + bhg (into g)
        launch_gemm(ci, Whl, bhl, nullptr, t, N, false, 0);
        launch_gemm(ci, Whg, bhg, nullptr, g, N, false, 0);
        // h = z * (g1 * sigmoid(g2)) + (1-z) * h
        combine_kernel<<<(ND + 255) / 256, 256>>>(h, z, t, g, ND);
    }

    // attention gate: t = h * sigmoid(h @ Wag + bag)
    {
        long long work = (long long)N * 32;
        att_kernel<<<(unsigned)((work + 255) / 256), 256>>>(h, Wag, bag, t, N);
    }
    // m = relu(t @ Wae + bae)
    launch_gemm(t, Wae, bae, nullptr, m, N, false, 2);

    // pooling
    zero_pool_kernel<<<(NGRAPH * D + 255) / 256, 256>>>(pmax, psum, cnt);
    {
        long long work = (long long)N * 32;
        pool_kernel<<<(unsigned)((work + 255) / 256), 256>>>(m, batch, pmax, psum, cnt, N);
    }
    // MLP head
    mlp_kernel<<<NGRAPH, D>>>(pmax, psum, cnt, W1, b1, W2, b2, out);
}